// round 10
// baseline (speedup 1.0000x reference)
#include <cuda_runtime.h>
#include <cstdint>

#define DMV  16
#define TILE 256

__device__ __forceinline__ float cayley_sign(int a, int b) {
    if (a & b & 8) return 0.0f;            // e3 * e3 = 0
    int s = 0;
    for (int t = a >> 1; t; t >>= 1) s += __popc(t & b);
    return (s & 1) ? -1.0f : 1.0f;
}
__device__ __forceinline__ uint32_t smem_u32(const void* p) {
    return (uint32_t)__cvta_generic_to_shared(p);
}
__device__ __forceinline__ void cp_async16(uint32_t s, const void* g) {
    asm volatile("cp.async.cg.shared.global [%0], [%1], 16;" :: "r"(s), "l"(g));
}

// ---------------------------------------------------------------------------
// Single fused kernel, one tile (256 rows) per block, grid (ceil(N/256), 32).
// Prologue: issue cp.async for this block's tile, then (while the DRAM fill is
// in flight) redundantly build the per-l constants P:
//   motor M = exp(-0.5*grade2(instr)) via 16-term Taylor (warp 0, shuffles),
//   fused sandwich S = Lmat@Rmat, grade-block packing (sandwich of an even
//   versor is grade-preserving and M~M = 1, so only the 4/6/4 blocks and the
//   collapsed color vectors survive).
// Body: R5-proven — swizzled SMEM, one row per thread, write back, staged
// coalesced streaming stores. Swizzle (c ^ ((r>>1)&3)) conflict-free both ways.
// ---------------------------------------------------------------------------
__global__ void __launch_bounds__(256, 6)
fused_kernel(const float* __restrict__ state,
             const float* __restrict__ instr,
             const float* __restrict__ remap,   // [4,10,10]
             const float* __restrict__ selw,    // [4,2]
             const float* __restrict__ selb,    // [4]
             float* __restrict__ out, int N)
{
    __shared__ __align__(16) float4 buf[TILE * 4];   // 16 KB
    __shared__ __align__(16) float P[112];
    // P: [0:16) G1 col-major {1,2,4,8} | [16:64) G2 col-major pad8
    //    {3,5,6,9,10,12} | [64:80) G3 {7,11,13,14} | [80:90) bc | [96:106) b0
    __shared__ float sgn[256];
    __shared__ float Mv[16], Mre[16], Sb[256], wv[4];

    const int l     = blockIdx.y;
    const int tid   = threadIdx.x;
    const int a     = tid >> 4;
    const int b     = tid & 15;
    const int tile0 = blockIdx.x * TILE;
    const int nvalid = min(TILE, N - tile0);

    const size_t gbase4 = ((size_t)l * N + tile0) * 4;
    const float4* gin  = reinterpret_cast<const float4*>(state) + gbase4;
    float4*       gout = reinterpret_cast<float4*>(out)   + gbase4;

    // ---- 1. kick off the tile load (flies during setup) ----
    #pragma unroll
    for (int k = 0; k < 4; k++) {
        int e = k * 256 + tid;
        int r = e >> 2, c = e & 3;
        if (r < nvalid)
            cp_async16(smem_u32(&buf[r * 4 + (c ^ ((r >> 1) & 3))]), gin + e);
    }
    asm volatile("cp.async.commit_group;");

    // ---- 2. setup: build P while the cp.async fill is in flight ----
    sgn[tid] = cayley_sign(a, b);
    __syncthreads();

    if (tid < 16) {                // Taylor exp on warp 0 lanes 0..15
        float xv   = (__popc(tid) == 2) ? -0.5f * instr[l * DMV + tid] : 0.0f;
        float term = (tid == 0) ? 1.0f : 0.0f;
        float acc  = term;
        for (int n = 1; n < 16; n++) {
            float nt = 0.0f;
            #pragma unroll
            for (int aa = 0; aa < 16; aa++) {
                float ta = __shfl_sync(0xFFFFu, term, aa);
                float xa = __shfl_sync(0xFFFFu, xv, aa ^ tid);
                nt = fmaf(ta * xa, sgn[aa * 16 + (aa ^ tid)], nt);
            }
            term = nt / (float)n;
            acc += term;
        }
        Mv[tid] = acc;
        int g = __popc(tid);
        Mre[tid] = acc * ((((g * (g - 1) / 2) & 1) != 0) ? -1.0f : 1.0f);
    } else if (tid == 32) {        // selector softmax on warp 1
        float s0 = instr[l * DMV + 0], s1 = instr[l * DMV + 15];
        float lg[4], m = -3.4e38f;
        #pragma unroll
        for (int k = 0; k < 4; k++) {
            lg[k] = fmaf(s0, selw[k * 2], fmaf(s1, selw[k * 2 + 1], selb[k]));
            m = fmaxf(m, lg[k]);
        }
        float sum = 0.0f;
        #pragma unroll
        for (int k = 0; k < 4; k++) { lg[k] = expf(lg[k] - m); sum += lg[k]; }
        #pragma unroll
        for (int k = 0; k < 4; k++) wv[k] = lg[k] / sum;
    }
    __syncthreads();

    {   // Sb[a][b] = sum_i Lm[a][i]*Rm[i][b], Lm/Rm expanded inline from M
        float s = 0.0f;
        #pragma unroll
        for (int i = 0; i < 16; i++)
            s += Mv[a ^ i] * sgn[(a ^ i) * 16 + a]
               * Mre[i ^ b] * sgn[i * 16 + (i ^ b)];
        Sb[tid] = s;
    }
    __syncthreads();

    {
        const int g1[4] = {1, 2, 4, 8};
        const int g2[6] = {3, 5, 6, 9, 10, 12};
        const int g3[4] = {7, 11, 13, 14};
        if (tid < 16) {
            int j = tid >> 2, i = tid & 3;
            P[tid] = Sb[g1[j] * 16 + g1[i]];
        } else if (tid < 64) {
            int t = tid - 16, j = t >> 3, i = t & 7;
            P[16 + t] = (i < 6) ? Sb[g2[j] * 16 + g2[i]] : 0.0f;
        } else if (tid < 80) {
            int t = tid - 64, j = t >> 2, i = t & 3;
            P[64 + t] = Sb[g3[j] * 16 + g3[i]];
        } else if (tid < 96) {     // collapsed color: bc
            int i = tid - 80;
            float v = 0.0f;
            if (i < 10) {
                #pragma unroll
                for (int k = 0; k < 4; k++) {
                    const float* tab = remap + k * 100 + i * 10;
                    float rowc = 0.0f;
                    #pragma unroll
                    for (int j = 0; j < 10; j++) rowc += tab[j] * (float)j;
                    v = fmaf(wv[k], rowc, v);
                }
            }
            P[tid] = v;
        } else if (tid < 112) {    // collapsed color: b0
            int i = tid - 96;
            float v = 0.0f;
            if (i < 10) {
                #pragma unroll
                for (int k = 0; k < 4; k++)
                    v = fmaf(wv[k], remap[k * 100 + i * 10], v);
            }
            P[tid] = v;
        }
    }

    // ---- 3. wait for tile, then compute ----
    asm volatile("cp.async.wait_group 0;" ::: "memory");
    __syncthreads();

    {
        const int r  = tid;
        const int sw = (r >> 1) & 3;
        float4 v0 = buf[r * 4 + (0 ^ sw)];
        float4 v1 = buf[r * 4 + (1 ^ sw)];
        float4 v2 = buf[r * 4 + (2 ^ sw)];
        float4 v3 = buf[r * 4 + (3 ^ sw)];

        const float x0 = v0.x, x1 = v0.y, x2  = v0.z, x3  = v0.w;
        const float x4 = v1.x, x5 = v1.y, x6  = v1.z, x7  = v1.w;
        const float x8 = v2.x, x9 = v2.y, x10 = v2.z, x11 = v2.w;
        const float x12 = v3.x, x13 = v3.y, x14 = v3.z;   // x15 unused

        const float4* P4 = reinterpret_cast<const float4*>(P);

        // grade-1 block
        float4 a0 = P4[0], a1 = P4[1], a2 = P4[2], a3 = P4[3];
        float y1 = fmaf(x8, a3.x, fmaf(x4, a2.x, fmaf(x2, a1.x, x1 * a0.x)));
        float y2 = fmaf(x8, a3.y, fmaf(x4, a2.y, fmaf(x2, a1.y, x1 * a0.y)));
        float y4 = fmaf(x8, a3.z, fmaf(x4, a2.z, fmaf(x2, a1.z, x1 * a0.z)));
        float y8 = fmaf(x8, a3.w, fmaf(x4, a2.w, fmaf(x2, a1.w, x1 * a0.w)));

        // grade-2 block
        float y3, y5, y6, y9, y10, y12;
        {
            float4 cA = P4[4], cB = P4[5];
            y3 = x3 * cA.x; y5 = x3 * cA.y; y6  = x3 * cA.z;
            y9 = x3 * cA.w; y10 = x3 * cB.x; y12 = x3 * cB.y;
        }
        {
            float4 cA = P4[6], cB = P4[7];
            y3 = fmaf(x5, cA.x, y3); y5  = fmaf(x5, cA.y, y5);  y6  = fmaf(x5, cA.z, y6);
            y9 = fmaf(x5, cA.w, y9); y10 = fmaf(x5, cB.x, y10); y12 = fmaf(x5, cB.y, y12);
        }
        {
            float4 cA = P4[8], cB = P4[9];
            y3 = fmaf(x6, cA.x, y3); y5  = fmaf(x6, cA.y, y5);  y6  = fmaf(x6, cA.z, y6);
            y9 = fmaf(x6, cA.w, y9); y10 = fmaf(x6, cB.x, y10); y12 = fmaf(x6, cB.y, y12);
        }
        {
            float4 cA = P4[10], cB = P4[11];
            y3 = fmaf(x9, cA.x, y3); y5  = fmaf(x9, cA.y, y5);  y6  = fmaf(x9, cA.z, y6);
            y9 = fmaf(x9, cA.w, y9); y10 = fmaf(x9, cB.x, y10); y12 = fmaf(x9, cB.y, y12);
        }
        {
            float4 cA = P4[12], cB = P4[13];
            y3 = fmaf(x10, cA.x, y3); y5  = fmaf(x10, cA.y, y5);  y6  = fmaf(x10, cA.z, y6);
            y9 = fmaf(x10, cA.w, y9); y10 = fmaf(x10, cB.x, y10); y12 = fmaf(x10, cB.y, y12);
        }
        {
            float4 cA = P4[14], cB = P4[15];
            y3 = fmaf(x12, cA.x, y3); y5  = fmaf(x12, cA.y, y5);  y6  = fmaf(x12, cA.z, y6);
            y9 = fmaf(x12, cA.w, y9); y10 = fmaf(x12, cB.x, y10); y12 = fmaf(x12, cB.y, y12);
        }

        // grade-3 block
        float4 h0 = P4[16], h1 = P4[17], h2 = P4[18], h3 = P4[19];
        float y7  = fmaf(x14, h3.x, fmaf(x13, h2.x, fmaf(x11, h1.x, x7 * h0.x)));
        float y11 = fmaf(x14, h3.y, fmaf(x13, h2.y, fmaf(x11, h1.y, x7 * h0.y)));
        float y13 = fmaf(x14, h3.z, fmaf(x13, h2.z, fmaf(x11, h1.z, x7 * h0.z)));
        float y14 = fmaf(x14, h3.w, fmaf(x13, h2.w, fmaf(x11, h1.w, x7 * h0.w)));

        // color unit from x0 (y0 == x0: M~M = 1, grade preserved)
        float raw = x0 * 9.0f;
        float cc = fminf(fmaxf(rintf(raw), 0.0f), 9.0f);
        float dm = raw - cc;
        float m = -4.0f * dm * dm;              // exact max of the 10 logits
        float se = 0.0f, nc = 0.0f, n0 = 0.0f;
        #pragma unroll
        for (int q = 0; q < 10; q++) {
            float t = raw - (float)q;
            float e = __expf(fmaf(-4.0f * t, t, -m));
            se += e;
            nc = fmaf(e, P[80 + q], nc);
            n0 = fmaf(e, P[96 + q], n0);
        }
        float inv = 1.0f / se;
        float out0  = nc * inv * (1.0f / 9.0f);
        float out15 = 1.0f - n0 * inv;

        // write own row back (exclusive ownership: no barrier needed here)
        buf[r * 4 + (0 ^ sw)] = make_float4(out0, y1,  y2,  y3);
        buf[r * 4 + (1 ^ sw)] = make_float4(y4,   y5,  y6,  y7);
        buf[r * 4 + (2 ^ sw)] = make_float4(y8,   y9,  y10, y11);
        buf[r * 4 + (3 ^ sw)] = make_float4(y12,  y13, y14, out15);
    }
    __syncthreads();

    // ---- 4. stage out: swizzled LDS -> coalesced streaming STG ----
    #pragma unroll
    for (int k = 0; k < 4; k++) {
        int e = k * 256 + tid;
        int r = e >> 2, c = e & 3;
        if (r < nvalid)
            __stcs(gout + e, buf[r * 4 + (c ^ ((r >> 1) & 3))]);
    }
}

extern "C" void kernel_launch(void* const* d_in, const int* in_sizes, int n_in,
                              void* d_out, int out_size)
{
    const float* state = (const float*)d_in[0];
    const float* instr = (const float*)d_in[1];
    const float* remap = (const float*)d_in[2];
    const float* selw  = (const float*)d_in[3];
    const float* selb  = (const float*)d_in[4];
    float* out = (float*)d_out;

    const int B = in_sizes[1] / DMV;            // 32
    const int N = in_sizes[0] / in_sizes[1];    // 100000

    dim3 grid((N + TILE - 1) / TILE, B);
    fused_kernel<<<grid, 256>>>(state, instr, remap, selw, selb, out, N);
}

// round 12
// speedup vs baseline: 2.2450x; 2.2450x over previous
#include <cuda_runtime.h>
#include <cstdint>

#define DMV  16
#define TILE 256
#define LBATCH 32

// Packed per-l constants, 112 floats each:
//  [0:16) G1 col-major {1,2,4,8} | [16:64) G2 col-major pad8 {3,5,6,9,10,12}
//  [64:80) G3 {7,11,13,14} | [80:90) bc (pad 96) | [96:106) b0 (pad 112)
__device__ float d_P[LBATCH][112];

__device__ __forceinline__ float cayley_sign(int a, int b) {
    if (a & b & 8) return 0.0f;            // e3 * e3 = 0
    int s = 0;
    for (int t = a >> 1; t; t >>= 1) s += __popc(t & b);
    return (s & 1) ? -1.0f : 1.0f;
}
__device__ __forceinline__ uint32_t smem_u32(const void* p) {
    return (uint32_t)__cvta_generic_to_shared(p);
}
__device__ __forceinline__ void cp_async16(uint32_t s, const void* g) {
    asm volatile("cp.async.cg.shared.global [%0], [%1], 16;" :: "r"(s), "l"(g));
}

// ---------------------------------------------------------------------------
// Setup: 32 blocks, 256 threads (R5-proven). Warp-shuffle Taylor exp ->
// fused sandwich -> grade-block packing + collapsed color vectors.
// Ends with threadfence + programmatic launch-completion trigger so the main
// kernel (launched with PDL) can overlap its cp.async prologue with us.
// ---------------------------------------------------------------------------
__global__ void setup_kernel(const float* __restrict__ instr,
                             const float* __restrict__ remap,   // [4,10,10]
                             const float* __restrict__ selw,    // [4,2]
                             const float* __restrict__ selb)    // [4]
{
    __shared__ float sgn[256];
    __shared__ float M[16], Mrev[16];
    __shared__ float Lm[256], Rm[256], Sb[256];
    __shared__ float w[4];

    const int l   = blockIdx.x;
    const int tid = threadIdx.x;
    const int a   = tid >> 4;
    const int b   = tid & 15;

    sgn[tid] = cayley_sign(a, b);
    __syncthreads();

    if (tid < 16) {
        const unsigned mask = 0x0000FFFFu;
        float iv   = instr[l * DMV + tid];
        float xv   = (__popc(tid) == 2) ? -0.5f * iv : 0.0f;
        float term = (tid == 0) ? 1.0f : 0.0f;
        float acc  = term;
        for (int n = 1; n < 16; n++) {
            float nt = 0.0f;
            #pragma unroll
            for (int aa = 0; aa < 16; aa++) {
                float ta = __shfl_sync(mask, term, aa);
                float xa = __shfl_sync(mask, xv, aa ^ tid);
                nt += ta * xa * sgn[aa * 16 + (aa ^ tid)];
            }
            term = nt / (float)n;
            acc += term;
        }
        M[tid] = acc;
        int g = __popc(tid);
        float rv = (((g * (g - 1) / 2) & 1) != 0) ? -1.0f : 1.0f;
        Mrev[tid] = acc * rv;
    }
    __syncthreads();

    Lm[tid] = M[a ^ b]    * sgn[(a ^ b) * 16 + a];
    Rm[tid] = Mrev[a ^ b] * sgn[a * 16 + (a ^ b)];
    __syncthreads();

    {
        float s = 0.0f;
        #pragma unroll
        for (int i = 0; i < 16; i++)
            s += Lm[a * 16 + i] * Rm[i * 16 + b];
        Sb[tid] = s;
    }

    if (tid == 0) {
        float s0 = instr[l * DMV + 0], s1 = instr[l * DMV + 15];
        float lg[4], m = -3.4e38f;
        #pragma unroll
        for (int k = 0; k < 4; k++) {
            lg[k] = s0 * selw[k * 2 + 0] + s1 * selw[k * 2 + 1] + selb[k];
            m = fmaxf(m, lg[k]);
        }
        float sum = 0.0f;
        #pragma unroll
        for (int k = 0; k < 4; k++) { lg[k] = expf(lg[k] - m); sum += lg[k]; }
        #pragma unroll
        for (int k = 0; k < 4; k++) w[k] = lg[k] / sum;
    }
    __syncthreads();

    const int g1[4] = {1, 2, 4, 8};
    const int g2[6] = {3, 5, 6, 9, 10, 12};
    const int g3[4] = {7, 11, 13, 14};

    if (tid < 16) {
        int j = tid >> 2, i = tid & 3;
        d_P[l][tid] = Sb[g1[j] * 16 + g1[i]];
    } else if (tid < 64) {
        int t = tid - 16, j = t >> 3, i = t & 7;
        d_P[l][16 + t] = (i < 6) ? Sb[g2[j] * 16 + g2[i]] : 0.0f;
    } else if (tid < 80) {
        int t = tid - 64, j = t >> 2, i = t & 3;
        d_P[l][64 + t] = Sb[g3[j] * 16 + g3[i]];
    } else if (tid < 112) {
        d_P[l][tid] = 0.0f;
    }

    if (tid < 10) {
        float bc = 0.0f, b0v = 0.0f;
        #pragma unroll
        for (int k = 0; k < 4; k++) {
            const float* tab = remap + k * 100 + tid * 10;
            float rowc = 0.0f;
            #pragma unroll
            for (int j = 0; j < 10; j++) rowc += tab[j] * (float)j;
            bc  += w[k] * rowc;
            b0v += w[k] * tab[0];
        }
        d_P[l][80 + tid] = bc;
        d_P[l][96 + tid] = b0v;
    }

    __threadfence();
    cudaTriggerProgrammaticLaunchCompletion();
}

// ---------------------------------------------------------------------------
// Main kernel (R5 body, unchanged except the PDL grid sync): cp.async
// coalesced stage-in -> swizzled SMEM -> one row per thread -> swizzled SMEM
// -> coalesced streaming STG. Swizzle (c ^ ((r>>1)&3)) conflict-free both ways.
// The cp.async prologue runs BEFORE the grid sync, overlapping with setup.
// ---------------------------------------------------------------------------
__global__ void __launch_bounds__(256, 6)
sandwich_color_kernel(const float* __restrict__ state,
                      float* __restrict__ out,
                      int N)
{
    __shared__ __align__(16) float4 buf[TILE * 4];   // 16 KB
    __shared__ __align__(16) float P[112];

    const int l     = blockIdx.y;
    const int tid   = threadIdx.x;
    const int tile0 = blockIdx.x * TILE;
    const int nvalid = min(TILE, N - tile0);

    const size_t gbase4 = ((size_t)l * N + tile0) * 4;   // float4 units
    const float4* gin  = reinterpret_cast<const float4*>(state) + gbase4;
    float4*       gout = reinterpret_cast<float4*>(out)   + gbase4;

    // stage in: coalesced cp.async -> swizzled SMEM (independent of setup)
    #pragma unroll
    for (int k = 0; k < 4; k++) {
        int e = k * TILE + tid;
        int r = e >> 2, c = e & 3;
        if (r < nvalid)
            cp_async16(smem_u32(&buf[r * 4 + (c ^ ((r >> 1) & 3))]), gin + e);
    }
    asm volatile("cp.async.commit_group;");

    // wait for the setup kernel's d_P writes (PDL), then pull P into SMEM
    cudaGridDependencySynchronize();
    if (tid < 112) P[tid] = d_P[l][tid];

    asm volatile("cp.async.wait_group 0;" ::: "memory");
    __syncthreads();

    {
        const int r  = tid;
        const int sw = (r >> 1) & 3;
        float4 v0 = buf[r * 4 + (0 ^ sw)];
        float4 v1 = buf[r * 4 + (1 ^ sw)];
        float4 v2 = buf[r * 4 + (2 ^ sw)];
        float4 v3 = buf[r * 4 + (3 ^ sw)];

        const float x0 = v0.x, x1 = v0.y, x2  = v0.z, x3  = v0.w;
        const float x4 = v1.x, x5 = v1.y, x6  = v1.z, x7  = v1.w;
        const float x8 = v2.x, x9 = v2.y, x10 = v2.z, x11 = v2.w;
        const float x12 = v3.x, x13 = v3.y, x14 = v3.z;   // x15 unused

        const float4* P4 = reinterpret_cast<const float4*>(P);

        // grade-1 block
        float4 a0 = P4[0], a1 = P4[1], a2 = P4[2], a3 = P4[3];
        float y1 = fmaf(x8, a3.x, fmaf(x4, a2.x, fmaf(x2, a1.x, x1 * a0.x)));
        float y2 = fmaf(x8, a3.y, fmaf(x4, a2.y, fmaf(x2, a1.y, x1 * a0.y)));
        float y4 = fmaf(x8, a3.z, fmaf(x4, a2.z, fmaf(x2, a1.z, x1 * a0.z)));
        float y8 = fmaf(x8, a3.w, fmaf(x4, a2.w, fmaf(x2, a1.w, x1 * a0.w)));

        // grade-2 block
        float y3, y5, y6, y9, y10, y12;
        {
            float4 cA = P4[4], cB = P4[5];
            y3 = x3 * cA.x; y5 = x3 * cA.y; y6  = x3 * cA.z;
            y9 = x3 * cA.w; y10 = x3 * cB.x; y12 = x3 * cB.y;
        }
        {
            float4 cA = P4[6], cB = P4[7];
            y3 = fmaf(x5, cA.x, y3); y5  = fmaf(x5, cA.y, y5);  y6  = fmaf(x5, cA.z, y6);
            y9 = fmaf(x5, cA.w, y9); y10 = fmaf(x5, cB.x, y10); y12 = fmaf(x5, cB.y, y12);
        }
        {
            float4 cA = P4[8], cB = P4[9];
            y3 = fmaf(x6, cA.x, y3); y5  = fmaf(x6, cA.y, y5);  y6  = fmaf(x6, cA.z, y6);
            y9 = fmaf(x6, cA.w, y9); y10 = fmaf(x6, cB.x, y10); y12 = fmaf(x6, cB.y, y12);
        }
        {
            float4 cA = P4[10], cB = P4[11];
            y3 = fmaf(x9, cA.x, y3); y5  = fmaf(x9, cA.y, y5);  y6  = fmaf(x9, cA.z, y6);
            y9 = fmaf(x9, cA.w, y9); y10 = fmaf(x9, cB.x, y10); y12 = fmaf(x9, cB.y, y12);
        }
        {
            float4 cA = P4[12], cB = P4[13];
            y3 = fmaf(x10, cA.x, y3); y5  = fmaf(x10, cA.y, y5);  y6  = fmaf(x10, cA.z, y6);
            y9 = fmaf(x10, cA.w, y9); y10 = fmaf(x10, cB.x, y10); y12 = fmaf(x10, cB.y, y12);
        }
        {
            float4 cA = P4[14], cB = P4[15];
            y3 = fmaf(x12, cA.x, y3); y5  = fmaf(x12, cA.y, y5);  y6  = fmaf(x12, cA.z, y6);
            y9 = fmaf(x12, cA.w, y9); y10 = fmaf(x12, cB.x, y10); y12 = fmaf(x12, cB.y, y12);
        }

        // grade-3 block
        float4 h0 = P4[16], h1 = P4[17], h2 = P4[18], h3 = P4[19];
        float y7  = fmaf(x14, h3.x, fmaf(x13, h2.x, fmaf(x11, h1.x, x7 * h0.x)));
        float y11 = fmaf(x14, h3.y, fmaf(x13, h2.y, fmaf(x11, h1.y, x7 * h0.y)));
        float y13 = fmaf(x14, h3.z, fmaf(x13, h2.z, fmaf(x11, h1.z, x7 * h0.z)));
        float y14 = fmaf(x14, h3.w, fmaf(x13, h2.w, fmaf(x11, h1.w, x7 * h0.w)));

        // color unit from x0 (y0 == x0: M~M = 1, grade preserved)
        float raw = x0 * 9.0f;
        float cc = fminf(fmaxf(rintf(raw), 0.0f), 9.0f);
        float dm = raw - cc;
        float m = -4.0f * dm * dm;                  // exact max of the 10 logits
        float se = 0.0f, nc = 0.0f, n0 = 0.0f;
        #pragma unroll
        for (int i = 0; i < 10; i++) {
            float t = raw - (float)i;
            float e = __expf(fmaf(-4.0f * t, t, -m));
            se += e;
            nc = fmaf(e, P[80 + i], nc);
            n0 = fmaf(e, P[96 + i], n0);
        }
        float inv = 1.0f / se;
        float out0  = nc * inv * (1.0f / 9.0f);
        float out15 = 1.0f - n0 * inv;

        // write own row back (exclusive ownership: no barrier needed here)
        buf[r * 4 + (0 ^ sw)] = make_float4(out0, y1,  y2,  y3);
        buf[r * 4 + (1 ^ sw)] = make_float4(y4,   y5,  y6,  y7);
        buf[r * 4 + (2 ^ sw)] = make_float4(y8,   y9,  y10, y11);
        buf[r * 4 + (3 ^ sw)] = make_float4(y12,  y13, y14, out15);
    }
    __syncthreads();

    // stage out: swizzled LDS -> coalesced streaming STG
    #pragma unroll
    for (int k = 0; k < 4; k++) {
        int e = k * TILE + tid;
        int r = e >> 2, c = e & 3;
        if (r < nvalid)
            __stcs(gout + e, buf[r * 4 + (c ^ ((r >> 1) & 3))]);
    }
}

extern "C" void kernel_launch(void* const* d_in, const int* in_sizes, int n_in,
                              void* d_out, int out_size)
{
    const float* state = (const float*)d_in[0];
    const float* instr = (const float*)d_in[1];
    const float* remap = (const float*)d_in[2];
    const float* selw  = (const float*)d_in[3];
    const float* selb  = (const float*)d_in[4];
    float* out = (float*)d_out;

    const int B = in_sizes[1] / DMV;            // 32
    const int N = in_sizes[0] / in_sizes[1];    // 100000

    setup_kernel<<<LBATCH, 256>>>(instr, remap, selw, selb);

    // Main kernel with programmatic dependent launch: its cp.async prologue
    // overlaps the setup kernel; cudaGridDependencySynchronize() gates d_P use.
    cudaLaunchConfig_t cfg = {};
    cfg.gridDim  = dim3((N + TILE - 1) / TILE, B);
    cfg.blockDim = dim3(256, 1, 1);
    cudaLaunchAttribute attrs[1];
    attrs[0].id = cudaLaunchAttributeProgrammaticStreamSerialization;
    attrs[0].val.programmaticStreamSerializationAllowed = 1;
    cfg.attrs = attrs;
    cfg.numAttrs = 1;
    cudaLaunchKernelEx(&cfg, sandwich_color_kernel, state, out, N);
}